// round 5
// baseline (speedup 1.0000x reference)
#include <cuda_runtime.h>
#include <math.h>
#include <cstdint>

// ---- Problem constants (fixed by dataset) ----
#define D        272
#define NC       19
#define NCPAD    32          // g_proj row stride: 128B-aligned rows (1 line/point in pool)
#define WPAD     24          // padded W row: 20 cols + 4 zeros -> 5 aligned float4 per k
#define THREADS  128
#define MAXROWS  65536
#define MAXNI    4096

typedef unsigned long long u64;

// ---- device scratch (no allocations allowed anywhere) ----
__device__ float g_proj[(size_t)MAXROWS * NCPAD];   // 8.4 MB (L2-resident in pool)
__device__ float g_Wpad[D * WPAD];                  // [272][24], cols 19..23 = 0
__device__ int   g_bound[MAXNI + 1];

// ---- packed f32x2 helpers (PTX-only) ----
__device__ __forceinline__ u64 pack2(float lo, float hi) {
    u64 r; asm("mov.b64 %0, {%1, %2};" : "=l"(r) : "f"(lo), "f"(hi)); return r;
}
__device__ __forceinline__ u64 fma2(u64 a, u64 b, u64 c) {
    u64 r; asm("fma.rn.f32x2 %0, %1, %2, %3;" : "=l"(r) : "l"(a), "l"(b), "l"(c)); return r;
}
__device__ __forceinline__ float2 unpack2(u64 v) {
    float2 f; asm("mov.b64 {%0, %1}, %2;" : "=f"(f.x), "=f"(f.y) : "l"(v)); return f;
}

union F4U2 { float4 f4; u64 u[2]; };

// ============================================================
// Pre-pass: g_Wpad[k][j] = W[k][j] (j<19), else 0.
// ============================================================
__global__ void wpad_kernel(const float* __restrict__ W) {
    int i = blockIdx.x * blockDim.x + threadIdx.x;
    if (i < D * WPAD) {
        int k = i / WPAD, j = i - k * WPAD;
        g_Wpad[i] = (j < NC) ? W[k * NC + j] : 0.0f;
    }
}

// ============================================================
// Pass 1: proj[row][0..19] = sum_k caps[row][k] * W[k][.]
// One thread = one row. W broadcast from smem, A direct from global
// with 17-deep LDG.128 bursts per 68-k chunk. No mainloop barriers.
// ============================================================
__global__ void __launch_bounds__(THREADS) proj_kernel(const float* __restrict__ caps) {
    __shared__ __align__(16) float s_W[D * WPAD];   // 26112 B

    const int tid = threadIdx.x;

    // Stage padded W (float4, coalesced)
    {
        const float4* ws = (const float4*)g_Wpad;
        float4* wd = (float4*)s_W;
#pragma unroll
        for (int i = tid; i < D * WPAD / 4; i += THREADS) wd[i] = ws[i];
    }
    __syncthreads();

    const size_t row = (size_t)blockIdx.x * THREADS + tid;
    const float4* src = (const float4*)&caps[row * D];    // 68 float4 per row

    u64 acc[10];
#pragma unroll
    for (int u = 0; u < 10; ++u) acc[u] = 0ull;

#pragma unroll 1
    for (int ch = 0; ch < 4; ++ch) {
        // Burst-load this chunk's 68 k-values: 17 independent LDG.128 (MLP=17)
        float4 a[17];
#pragma unroll
        for (int i = 0; i < 17; ++i) a[i] = src[ch * 17 + i];

#pragma unroll
        for (int i = 0; i < 17; ++i) {
            const int kbase = ch * 68 + i * 4;
#pragma unroll
            for (int e = 0; e < 4; ++e) {
                const float av = (e == 0) ? a[i].x : (e == 1) ? a[i].y
                               : (e == 2) ? a[i].z : a[i].w;
                const u64 p = pack2(av, av);
                const float4* w = (const float4*)&s_W[(kbase + e) * WPAD];
                F4U2 w0, w1, w2, w3, w4;
                w0.f4 = w[0]; w1.f4 = w[1]; w2.f4 = w[2]; w3.f4 = w[3]; w4.f4 = w[4];
                acc[0] = fma2(p, w0.u[0], acc[0]);
                acc[1] = fma2(p, w0.u[1], acc[1]);
                acc[2] = fma2(p, w1.u[0], acc[2]);
                acc[3] = fma2(p, w1.u[1], acc[3]);
                acc[4] = fma2(p, w2.u[0], acc[4]);
                acc[5] = fma2(p, w2.u[1], acc[5]);
                acc[6] = fma2(p, w3.u[0], acc[6]);
                acc[7] = fma2(p, w3.u[1], acc[7]);
                acc[8] = fma2(p, w4.u[0], acc[8]);
                acc[9] = fma2(p, w4.u[1], acc[9]);
            }
        }
    }

    // Writeback: 5 STG.128 into a 128B-aligned row
    float* op = &g_proj[row * NCPAD];
#pragma unroll
    for (int u = 0; u < 5; ++u) {
        float2 lo = unpack2(acc[2 * u]);
        float2 hi = unpack2(acc[2 * u + 1]);
        float4 v; v.x = lo.x; v.y = lo.y; v.z = hi.x; v.w = hi.y;
        *(float4*)&op[4 * u] = v;
    }
}

// ============================================================
// Segment boundaries from sorted segment_ids (handles empties).
// ============================================================
__global__ void bounds_kernel(const int* __restrict__ seg, int P, int NI) {
    int p = blockIdx.x * blockDim.x + threadIdx.x;
    if (p >= P) return;
    int cur  = seg[p];
    int prev = (p == 0) ? -1 : seg[p - 1];
    for (int s = prev + 1; s <= cur; ++s) g_bound[s] = p;
    if (p == P - 1)
        for (int s = cur + 1; s <= NI; ++s) g_bound[s] = P;
}

// ============================================================
// Pass 2: warp per segment, lane per point (MLP=5/lane), shfl reduce.
// ============================================================
__global__ void __launch_bounds__(256) pool_kernel(const int* __restrict__ point_idx,
                                                   const float* __restrict__ bias,
                                                   float* __restrict__ out, int NI) {
    int warp = (blockIdx.x * blockDim.x + threadIdx.x) >> 5;
    int lane = threadIdx.x & 31;
    if (warp >= NI) return;

    int start = g_bound[warp];
    int end   = g_bound[warp + 1];

    float v[20];
#pragma unroll
    for (int c = 0; c < 20; ++c) v[c] = 0.0f;

    for (int p = start + lane; p < end; p += 32) {
        int idx = point_idx[p];
        const float4* r = (const float4*)&g_proj[(size_t)idx * NCPAD];
        float4 a = r[0], b = r[1], c4 = r[2], d4 = r[3], e = r[4];
        v[0]  += a.x;  v[1]  += a.y;  v[2]  += a.z;  v[3]  += a.w;
        v[4]  += b.x;  v[5]  += b.y;  v[6]  += b.z;  v[7]  += b.w;
        v[8]  += c4.x; v[9]  += c4.y; v[10] += c4.z; v[11] += c4.w;
        v[12] += d4.x; v[13] += d4.y; v[14] += d4.z; v[15] += d4.w;
        v[16] += e.x;  v[17] += e.y;  v[18] += e.z;  v[19] += e.w;
    }

#pragma unroll
    for (int off = 16; off > 0; off >>= 1)
#pragma unroll
        for (int c = 0; c < 20; ++c)
            v[c] += __shfl_xor_sync(0xFFFFFFFFu, v[c], off);

    if (lane == 0) {
        int cnt = end - start;
        float inv = 1.0f / (float)(cnt > 0 ? cnt : 1);
        float* op = &out[(size_t)warp * NC];
#pragma unroll
        for (int c = 0; c < NC; ++c) {
            float x = v[c] * inv + bias[c];
            op[c] = 1.0f / (1.0f + expf(-x));
        }
    }
}

// ============================================================
extern "C" void kernel_launch(void* const* d_in, const int* in_sizes, int n_in,
                              void* d_out, int out_size) {
    const float* caps = (const float*)d_in[0];   // [65536, 272]
    const float* Wm   = (const float*)d_in[1];   // [272, 19]
    const float* bias = (const float*)d_in[2];   // [19]
    const int*   pidx = (const int*)d_in[3];     // [P]
    const int*   seg  = (const int*)d_in[4];     // [P] sorted

    const int P     = in_sizes[3];
    const int NI    = out_size / NC;             // 4096
    const int nrows = in_sizes[0] / D;           // 65536

    wpad_kernel<<<(D * WPAD + 255) / 256, 256>>>(Wm);
    bounds_kernel<<<(P + 255) / 256, 256>>>(seg, P, NI);
    proj_kernel<<<nrows / THREADS, THREADS>>>(caps);
    pool_kernel<<<(NI * 32 + 255) / 256, 256>>>(pidx, bias, (float*)d_out, NI);
}